// round 2
// baseline (speedup 1.0000x reference)
#include <cuda_runtime.h>

#define NPTS 4096
#define NW 128          // 4096/32 words per conflict row
#define NPROB 4         // (b, class) pairs: 2 batches x 2 classes

static __device__ float4   g_pos_u[NPROB][NPTS];        // unsorted positions (z,y,x,-)
static __device__ float4   g_pos_s[NPROB][NPTS];        // sorted positions   (z,y,x,aa)
static __device__ float4   g_alist[NPROB][NPTS];        // compacted alive    (z,y,x,aa)
static __device__ unsigned g_conflict[NPROB][NPTS * NW];// predecessor-conflict bitmask rows
static __device__ int      g_M[NPROB];                  // valid count per problem
static __device__ int      g_acount[NPROB];             // alive count per problem
static __device__ int      g_cnt[NPROB][3];             // tp, lp, lt accumulators

// XLA expands logistic(x) = 0.5 + 0.5*tanh(0.5*x); tanh uses Eigen's rational approx.
__device__ __forceinline__ float xla_logistic(float x) {
    float t  = 0.5f * x;
    float ax = fabsf(t);
    float xc = fminf(fmaxf(t, -7.90531110763549805f), 7.90531110763549805f);
    float x2 = xc * xc;
    float p = fmaf(x2, -2.76076847742355e-16f, 2.00018790482477e-13f);
    p = fmaf(x2, p, -8.60467152213735e-11f);
    p = fmaf(x2, p,  5.12229709037114e-08f);
    p = fmaf(x2, p,  1.48572235717979e-05f);
    p = fmaf(x2, p,  6.37261928875436e-04f);
    p = fmaf(x2, p,  4.89352455891786e-03f);
    p = xc * p;
    float q = fmaf(x2, 1.19825839466702e-06f, 1.18534705686654e-04f);
    q = fmaf(x2, q, 2.26843463243900e-03f);
    q = fmaf(x2, q, 4.89352518554385e-03f);
    float y = p / q;
    if (ax < 0.0004f) y = t;           // tiny-argument shortcut like XLA/Eigen
    return __fadd_rn(__fmul_rn(0.5f, y), 0.5f);
}

// ---------------------------------------------------------------------------
// Kernel 1: per-problem prep (conf/argmax, positions, sort keys) + bitonic sort
// ---------------------------------------------------------------------------
__global__ __launch_bounds__(1024, 1) void k_prep_sort(
    const float* __restrict__ pred_clses,
    const float* __restrict__ pred_boxes)
{
    __shared__ unsigned long long skey[NPTS];   // 32 KB
    __shared__ int sM;

    int prob = blockIdx.x;
    int b    = prob >> 1;
    int cls  = (prob & 1) + 1;
    int tid  = threadIdx.x;

    if (tid == 0) sM = 0;
    if (tid < 3)  g_cnt[prob][tid] = 0;
    __syncthreads();

    int vcount = 0;
    for (int n = tid; n < NPTS; n += 1024) {
        float cv0 = pred_clses[(b * 3 + 0) * NPTS + n];
        float cv1 = pred_clses[(b * 3 + 1) * NPTS + n];
        float cv2 = pred_clses[(b * 3 + 2) * NPTS + n];
        float conf = cv0; int arg = 0;
        if (cv1 > conf) { conf = cv1; arg = 1; }
        if (cv2 > conf) { conf = cv2; arg = 2; }
        bool valid = (arg == cls);
        if (valid) vcount++;
        if (!valid) conf = __int_as_float(0xff800000); // -inf
        // descending conf, ascending index tiebreak -> ascending 64-bit key
        unsigned cb  = __float_as_uint(conf);
        unsigned ord = cb ^ ((cb & 0x80000000u) ? 0xFFFFFFFFu : 0x80000000u);
        skey[n] = (((unsigned long long)(~ord)) << 32) | (unsigned)n;

        int d = n >> 10, h = (n >> 5) & 31, w = n & 31;
        float bz = pred_boxes[(b * 3 + 0) * NPTS + n];
        float by = pred_boxes[(b * 3 + 1) * NPTS + n];
        float bx = pred_boxes[(b * 3 + 2) * NPTS + n];
        float sz = xla_logistic(bz);
        float sy = xla_logistic(by);
        float sx = xla_logistic(bx);
        float pz = __fmul_rn(__fdiv_rn(__fadd_rn((float)d, sz),  4.0f),  3.0f);
        float py = __fmul_rn(__fdiv_rn(__fadd_rn((float)h, sy), 32.0f), 25.0f);
        float px = __fmul_rn(__fdiv_rn(__fadd_rn((float)w, sx), 32.0f), 25.0f);
        g_pos_u[prob][n] = make_float4(pz, py, px, 0.0f);
    }
    atomicAdd(&sM, vcount);
    __syncthreads();

    // bitonic sort, ascending, 4096 elements
    for (int k = 2; k <= NPTS; k <<= 1) {
        for (int j = k >> 1; j > 0; j >>= 1) {
            for (int i = tid; i < NPTS; i += 1024) {
                int ixj = i ^ j;
                if (ixj > i) {
                    unsigned long long a = skey[i], c = skey[ixj];
                    bool up = ((i & k) == 0);
                    if (up ? (a > c) : (a < c)) { skey[i] = c; skey[ixj] = a; }
                }
            }
            __syncthreads();
        }
    }

    // gather sorted positions + precompute aa = z^2 + y^2 + x^2 (left-assoc)
    for (int s = tid; s < NPTS; s += 1024) {
        int idx = (int)(skey[s] & 0xFFFFFFFFu);
        float4 p = g_pos_u[prob][idx];
        p.w = __fadd_rn(__fadd_rn(__fmul_rn(p.x, p.x), __fmul_rn(p.y, p.y)),
                        __fmul_rn(p.z, p.z));
        g_pos_s[prob][s] = p;
    }
    if (tid == 0) g_M[prob] = sM;
}

// ---------------------------------------------------------------------------
// Kernel 2: conflict bitmask build — warp per row j, ballot assembles words
// row j, word w, bit t  <=>  i = 32*w + t < j conflicts with j (both valid)
// ---------------------------------------------------------------------------
__global__ __launch_bounds__(256) void k_conflict()
{
    int prob = blockIdx.y;
    int M    = g_M[prob];
    float c2 = (prob & 1) ? 0.5625f : 1.0f;   // cutoff^2 (0.75^2, 1.0^2)
    int lane = threadIdx.x & 31;
    int gw   = blockIdx.x * (blockDim.x >> 5) + (threadIdx.x >> 5);
    int nwarps = gridDim.x * (blockDim.x >> 5);
    const float4* pos = g_pos_s[prob];
    unsigned* cf = g_conflict[prob];

    for (int j = gw + 1; j < M; j += nwarps) {
        float4 pj = pos[j];
        int wend = (j - 1) >> 5;
        for (int w = 0; w <= wend; w++) {
            int i = (w << 5) + lane;
            bool hit = false;
            if (i < j) {
                float4 pi = pos[i];
                float dot = __fadd_rn(__fadd_rn(__fmul_rn(pi.x, pj.x),
                                                __fmul_rn(pi.y, pj.y)),
                                      __fmul_rn(pi.z, pj.z));
                float dist = __fsub_rn(__fadd_rn(pi.w, pj.w), __fmul_rn(2.0f, dot));
                hit = dist < c2;
            }
            unsigned bits = __ballot_sync(0xFFFFFFFFu, hit);
            if (lane == 0) cf[(size_t)j * NW + w] = bits;
        }
    }
}

// ---------------------------------------------------------------------------
// Kernel 3: NMS iterations (existence-check bitset form, exact early exit)
// plus compaction of survivors and lp count
// ---------------------------------------------------------------------------
__global__ __launch_bounds__(1024, 1) void k_nms()
{
    __shared__ unsigned alive[NW], Fb[NW], NA[NW];
    __shared__ int sChanged, sCount, sLP;

    int prob = blockIdx.x;
    int tid  = threadIdx.x;
    int M    = g_M[prob];

    if (tid < NW) {
        int fullw = M >> 5, rem = M & 31;
        unsigned v = 0;
        if (tid < fullw) v = 0xFFFFFFFFu;
        else if (tid == fullw && rem) v = (1u << rem) - 1u;
        alive[tid] = v;
    }
    if (tid == 0) { sCount = 0; sLP = 0; sChanged = 0; }
    __syncthreads();

    const unsigned* cf = g_conflict[prob];

    for (int it = 0; it < 32; it++) {
        if (tid == 0) sChanged = 0;
        // pass 1: F_s = alive_s && (no alive conflicting predecessor)
        for (int s = tid; s < NPTS; s += 1024) {
            bool f = false;
            if ((alive[s >> 5] >> (s & 31)) & 1) {
                f = true;
                if (s > 0) {
                    int wend = (s - 1) >> 5;
                    const unsigned* row = cf + (size_t)s * NW;
                    for (int w = 0; w <= wend; w++)
                        if (row[w] & alive[w]) { f = false; break; }
                }
            }
            unsigned bal = __ballot_sync(0xFFFFFFFFu, f);
            if ((tid & 31) == 0) Fb[s >> 5] = bal;
        }
        __syncthreads();
        // pass 2: alive_s &= no conflicting predecessor in F
        for (int s = tid; s < NPTS; s += 1024) {
            bool a = false;
            if ((alive[s >> 5] >> (s & 31)) & 1) {
                a = true;
                if (s > 0) {
                    int wend = (s - 1) >> 5;
                    const unsigned* row = cf + (size_t)s * NW;
                    for (int w = 0; w <= wend; w++)
                        if (row[w] & Fb[w]) { a = false; break; }
                }
            }
            unsigned bal = __ballot_sync(0xFFFFFFFFu, a);
            if ((tid & 31) == 0) NA[s >> 5] = bal;
        }
        __syncthreads();
        if (tid < NW) {
            if (NA[tid] != alive[tid]) sChanged = 1;
            alive[tid] = NA[tid];
        }
        __syncthreads();
        int stop = (sChanged == 0);   // fixed point => all later iters identical
        __syncthreads();
        if (stop) break;
    }

    // compact survivors; count lp with z-range filter
    const float HI = (float)(3.0 + 1e-05);
    for (int s = tid; s < M; s += 1024) {
        if ((alive[s >> 5] >> (s & 31)) & 1) {
            float4 p = g_pos_s[prob][s];
            int id = atomicAdd(&sCount, 1);
            g_alist[prob][id] = p;
            if (p.x >= 0.0f && p.x < HI) atomicAdd(&sLP, 1);
        }
    }
    __syncthreads();
    if (tid == 0) { g_acount[prob] = sCount; g_cnt[prob][1] = sLP; }
}

// ---------------------------------------------------------------------------
// Kernel 4: target matching — thread per target, scan compacted alive list
// ---------------------------------------------------------------------------
__global__ __launch_bounds__(256) void k_match(
    const int*   __restrict__ targ_clses,
    const float* __restrict__ targ_boxes)
{
    __shared__ int sLT, sTP;
    int prob = blockIdx.y;
    int b    = prob >> 1;
    int cls  = (prob & 1) + 1;
    float c2 = (prob & 1) ? 0.5625f : 1.0f;
    const float HI = (float)(3.0 + 1e-05);
    int tid = threadIdx.x;
    if (tid == 0) { sLT = 0; sTP = 0; }
    __syncthreads();

    int n = blockIdx.x * 256 + tid;
    int lt = 0, tp = 0;
    if (n < NPTS && targ_clses[b * NPTS + n] == cls) {
        int d = n >> 10, h = (n >> 5) & 31, w = n & 31;
        float t0 = targ_boxes[(b * NPTS + n) * 3 + 0];
        float t1 = targ_boxes[(b * NPTS + n) * 3 + 1];
        float t2 = targ_boxes[(b * NPTS + n) * 3 + 2];
        float tz = __fmul_rn(__fdiv_rn(__fadd_rn((float)d, t0),  4.0f),  3.0f);
        float ty = __fmul_rn(__fdiv_rn(__fadd_rn((float)h, t1), 32.0f), 25.0f);
        float tx = __fmul_rn(__fdiv_rn(__fadd_rn((float)w, t2), 32.0f), 25.0f);
        if (tz >= 0.0f && tz < HI) {
            lt = 1;
            float bb = __fadd_rn(__fadd_rn(__fmul_rn(tz, tz), __fmul_rn(ty, ty)),
                                 __fmul_rn(tx, tx));
            int A = g_acount[prob];
            const float4* al = g_alist[prob];
            for (int a = 0; a < A; a++) {
                float4 p = al[a];
                float dot = __fadd_rn(__fadd_rn(__fmul_rn(p.x, tz),
                                                __fmul_rn(p.y, ty)),
                                      __fmul_rn(p.z, tx));
                float dist = __fsub_rn(__fadd_rn(p.w, bb), __fmul_rn(2.0f, dot));
                if (dist < c2) { tp = 1; break; }
            }
        }
    }
    if (lt) atomicAdd(&sLT, 1);
    if (tp) atomicAdd(&sTP, 1);
    __syncthreads();
    if (tid == 0) {
        if (sLT) atomicAdd(&g_cnt[prob][2], sLT);
        if (sTP) atomicAdd(&g_cnt[prob][0], sTP);
    }
}

// ---------------------------------------------------------------------------
// Kernel 5: finalize — out[(b*2+ci)*3 + {0,1,2}] = {tp, fp, fn} AS FLOAT32
// (reference counts are cast to float32 by the harness; writing raw int bits
//  made negative fp/fn reinterpret as NaN -> rel_err nan last round)
// ---------------------------------------------------------------------------
__global__ void k_final(float* __restrict__ out)
{
    int p = threadIdx.x;
    if (p < NPROB) {
        int tp = g_cnt[p][0], lp = g_cnt[p][1], lt = g_cnt[p][2];
        out[p * 3 + 0] = (float)tp;
        out[p * 3 + 1] = (float)(lp - tp);
        out[p * 3 + 2] = (float)(lt - tp);
    }
}

extern "C" void kernel_launch(void* const* d_in, const int* in_sizes, int n_in,
                              void* d_out, int out_size)
{
    const float* pred_clses = (const float*)d_in[0];
    const float* pred_boxes = (const float*)d_in[1];
    const int*   targ_clses = (const int*)d_in[2];
    const float* targ_boxes = (const float*)d_in[3];
    float* out = (float*)d_out;

    k_prep_sort<<<NPROB, 1024>>>(pred_clses, pred_boxes);
    k_conflict<<<dim3(32, NPROB), 256>>>();
    k_nms<<<NPROB, 1024>>>();
    k_match<<<dim3(16, NPROB), 256>>>(targ_clses, targ_boxes);
    k_final<<<1, 32>>>(out);
}

// round 3
// speedup vs baseline: 1.9290x; 1.9290x over previous
#include <cuda_runtime.h>

#define NPTS 4096
#define NW 128          // 4096/32 words per conflict row
#define NPROB 4         // (b, class) pairs: 2 batches x 2 classes

static __device__ float4   g_pos_u[NPROB][NPTS];        // unsorted positions (z,y,x,-)
static __device__ float4   g_pos_s[NPROB][NPTS];        // sorted positions   (z,y,x,aa)
static __device__ float4   g_alist[NPROB][NPTS];        // compacted alive    (z,y,x,aa)
static __device__ unsigned g_conflict[NPROB][NPTS * NW];// predecessor-conflict bitmask rows
static __device__ int      g_M[NPROB];                  // valid count per problem
static __device__ int      g_acount[NPROB];             // alive count per problem
static __device__ int      g_cnt[NPROB][3];             // tp, lp, lt accumulators

// XLA expands logistic(x) = 0.5 + 0.5*tanh(0.5*x); tanh uses Eigen's rational approx.
__device__ __forceinline__ float xla_logistic(float x) {
    float t  = 0.5f * x;
    float ax = fabsf(t);
    float xc = fminf(fmaxf(t, -7.90531110763549805f), 7.90531110763549805f);
    float x2 = xc * xc;
    float p = fmaf(x2, -2.76076847742355e-16f, 2.00018790482477e-13f);
    p = fmaf(x2, p, -8.60467152213735e-11f);
    p = fmaf(x2, p,  5.12229709037114e-08f);
    p = fmaf(x2, p,  1.48572235717979e-05f);
    p = fmaf(x2, p,  6.37261928875436e-04f);
    p = fmaf(x2, p,  4.89352455891786e-03f);
    p = xc * p;
    float q = fmaf(x2, 1.19825839466702e-06f, 1.18534705686654e-04f);
    q = fmaf(x2, q, 2.26843463243900e-03f);
    q = fmaf(x2, q, 4.89352518554385e-03f);
    float y = p / q;
    if (ax < 0.0004f) y = t;
    return __fadd_rn(__fmul_rn(0.5f, y), 0.5f);
}

// ---------------------------------------------------------------------------
// Kernel 1: prep (conf/argmax, positions), compact valid, bitonic-sort only
// the valid subset (padded to next pow2). Invalid entries never matter.
// ---------------------------------------------------------------------------
__global__ __launch_bounds__(1024, 1) void k_prep_sort(
    const float* __restrict__ pred_clses,
    const float* __restrict__ pred_boxes)
{
    __shared__ unsigned long long skey[NPTS];   // 32 KB
    __shared__ int sM;

    int prob = blockIdx.x;
    int b    = prob >> 1;
    int cls  = (prob & 1) + 1;
    int tid  = threadIdx.x;

    if (tid == 0) sM = 0;
    if (tid < 3)  g_cnt[prob][tid] = 0;
    __syncthreads();

    for (int n = tid; n < NPTS; n += 1024) {
        float cv0 = pred_clses[(b * 3 + 0) * NPTS + n];
        float cv1 = pred_clses[(b * 3 + 1) * NPTS + n];
        float cv2 = pred_clses[(b * 3 + 2) * NPTS + n];
        float conf = cv0; int arg = 0;
        if (cv1 > conf) { conf = cv1; arg = 1; }
        if (cv2 > conf) { conf = cv2; arg = 2; }
        bool valid = (arg == cls);
        if (valid) {
            // descending conf, ascending index tiebreak -> ascending 64-bit key
            unsigned cb  = __float_as_uint(conf);
            unsigned ord = cb ^ ((cb & 0x80000000u) ? 0xFFFFFFFFu : 0x80000000u);
            int slot = atomicAdd(&sM, 1);
            skey[slot] = (((unsigned long long)(~ord)) << 32) | (unsigned)n;
        }
        int d = n >> 10, h = (n >> 5) & 31, w = n & 31;
        float bz = pred_boxes[(b * 3 + 0) * NPTS + n];
        float by = pred_boxes[(b * 3 + 1) * NPTS + n];
        float bx = pred_boxes[(b * 3 + 2) * NPTS + n];
        float sz = xla_logistic(bz);
        float sy = xla_logistic(by);
        float sx = xla_logistic(bx);
        float pz = __fmul_rn(__fdiv_rn(__fadd_rn((float)d, sz),  4.0f),  3.0f);
        float py = __fmul_rn(__fdiv_rn(__fadd_rn((float)h, sy), 32.0f), 25.0f);
        float px = __fmul_rn(__fdiv_rn(__fadd_rn((float)w, sx), 32.0f), 25.0f);
        g_pos_u[prob][n] = make_float4(pz, py, px, 0.0f);
    }
    __syncthreads();

    int M = sM;
    int P = 1;
    while (P < M) P <<= 1;            // P = next pow2 >= M (P <= 4096)
    if (P < 2) P = 2;

    // pad to P with +inf keys
    for (int s = M + tid; s < P; s += 1024)
        skey[s] = 0xFFFFFFFFFFFFFFFFull;
    __syncthreads();

    // bitonic sort, ascending, P elements
    for (int k = 2; k <= P; k <<= 1) {
        for (int j = k >> 1; j > 0; j >>= 1) {
            for (int i = tid; i < P; i += 1024) {
                int ixj = i ^ j;
                if (ixj > i) {
                    unsigned long long a = skey[i], c = skey[ixj];
                    bool up = ((i & k) == 0);
                    if (up ? (a > c) : (a < c)) { skey[i] = c; skey[ixj] = a; }
                }
            }
            __syncthreads();
        }
    }

    // gather sorted positions + precompute aa = z^2 + y^2 + x^2 (left-assoc)
    for (int s = tid; s < M; s += 1024) {
        int idx = (int)(skey[s] & 0xFFFFFFFFu);
        float4 p = g_pos_u[prob][idx];
        p.w = __fadd_rn(__fadd_rn(__fmul_rn(p.x, p.x), __fmul_rn(p.y, p.y)),
                        __fmul_rn(p.z, p.z));
        g_pos_s[prob][s] = p;
    }
    if (tid == 0) g_M[prob] = M;
}

// ---------------------------------------------------------------------------
// Kernel 2: conflict bitmask build — warp per row j, ballot assembles words
// ---------------------------------------------------------------------------
__global__ __launch_bounds__(256) void k_conflict()
{
    int prob = blockIdx.y;
    int M    = g_M[prob];
    float c2 = (prob & 1) ? 0.5625f : 1.0f;   // cutoff^2 (0.75^2, 1.0^2)
    int lane = threadIdx.x & 31;
    int gw   = blockIdx.x * (blockDim.x >> 5) + (threadIdx.x >> 5);
    int nwarps = gridDim.x * (blockDim.x >> 5);
    const float4* pos = g_pos_s[prob];
    unsigned* cf = g_conflict[prob];

    for (int j = gw + 1; j < M; j += nwarps) {
        float4 pj = pos[j];
        int wend = (j - 1) >> 5;
        for (int w = 0; w <= wend; w++) {
            int i = (w << 5) + lane;
            bool hit = false;
            if (i < j) {
                float4 pi = pos[i];
                float dot = __fadd_rn(__fadd_rn(__fmul_rn(pi.x, pj.x),
                                                __fmul_rn(pi.y, pj.y)),
                                      __fmul_rn(pi.z, pj.z));
                float dist = __fsub_rn(__fadd_rn(pi.w, pj.w), __fmul_rn(2.0f, dot));
                hit = dist < c2;
            }
            unsigned bits = __ballot_sync(0xFFFFFFFFu, hit);
            if (lane == 0) cf[(size_t)j * NW + w] = bits;
        }
    }
}

// ---------------------------------------------------------------------------
// Kernel 3: NMS iterations (existence-check bitset form, exact early exit)
// ---------------------------------------------------------------------------
__global__ __launch_bounds__(1024, 1) void k_nms()
{
    __shared__ unsigned alive[NW], Fb[NW], NA[NW];
    __shared__ int sChanged, sCount, sLP;

    int prob = blockIdx.x;
    int tid  = threadIdx.x;
    int M    = g_M[prob];
    int Mc   = (M + 31) & ~31;        // warp-uniform loop bound

    if (tid < NW) {
        int fullw = M >> 5, rem = M & 31;
        unsigned v = 0;
        if (tid < fullw) v = 0xFFFFFFFFu;
        else if (tid == fullw && rem) v = (1u << rem) - 1u;
        alive[tid] = v;
    }
    if (tid == 0) { sCount = 0; sLP = 0; sChanged = 0; }
    __syncthreads();

    const unsigned* cf = g_conflict[prob];

    for (int it = 0; it < 32; it++) {
        if (tid == 0) sChanged = 0;
        // pass 1: F_s = alive_s && (no alive conflicting predecessor)
        for (int s = tid; s < Mc; s += 1024) {
            bool f = false;
            if (s < M && ((alive[s >> 5] >> (s & 31)) & 1)) {
                f = true;
                if (s > 0) {
                    int wend = (s - 1) >> 5;
                    const unsigned* row = cf + (size_t)s * NW;
                    for (int w = 0; w <= wend; w++)
                        if (row[w] & alive[w]) { f = false; break; }
                }
            }
            unsigned bal = __ballot_sync(0xFFFFFFFFu, f);
            if ((tid & 31) == 0) Fb[s >> 5] = bal;
        }
        __syncthreads();
        // pass 2: alive_s &= no conflicting predecessor in F
        for (int s = tid; s < Mc; s += 1024) {
            bool a = false;
            if (s < M && ((alive[s >> 5] >> (s & 31)) & 1)) {
                a = true;
                if (s > 0) {
                    int wend = (s - 1) >> 5;
                    const unsigned* row = cf + (size_t)s * NW;
                    for (int w = 0; w <= wend; w++)
                        if (row[w] & Fb[w]) { a = false; break; }
                }
            }
            unsigned bal = __ballot_sync(0xFFFFFFFFu, a);
            if ((tid & 31) == 0) NA[s >> 5] = bal;
        }
        __syncthreads();
        if (tid < NW) {
            if (NA[tid] != alive[tid]) sChanged = 1;
            alive[tid] = NA[tid];
        }
        __syncthreads();
        int stop = (sChanged == 0);   // fixed point => all later iters identical
        __syncthreads();
        if (stop) break;
    }

    // compact survivors; count lp with z-range filter
    const float HI = (float)(3.0 + 1e-05);
    for (int s = tid; s < M; s += 1024) {
        if ((alive[s >> 5] >> (s & 31)) & 1) {
            float4 p = g_pos_s[prob][s];
            int id = atomicAdd(&sCount, 1);
            g_alist[prob][id] = p;
            if (p.x >= 0.0f && p.x < HI) atomicAdd(&sLP, 1);
        }
    }
    __syncthreads();
    if (tid == 0) { g_acount[prob] = sCount; g_cnt[prob][1] = sLP; }
}

// ---------------------------------------------------------------------------
// Kernel 4: target matching — WARP per target, lanes scan alive list in
// 256-entry chunks (8 coalesced float4 loads per lane before each ballot)
// ---------------------------------------------------------------------------
__global__ __launch_bounds__(256) void k_match(
    const int*   __restrict__ targ_clses,
    const float* __restrict__ targ_boxes)
{
    int prob = blockIdx.y;
    int b    = prob >> 1;
    int cls  = (prob & 1) + 1;
    float c2 = (prob & 1) ? 0.5625f : 1.0f;
    const float HI = (float)(3.0 + 1e-05);

    int lane   = threadIdx.x & 31;
    int warp   = blockIdx.x * (blockDim.x >> 5) + (threadIdx.x >> 5);
    int nwarps = gridDim.x * (blockDim.x >> 5);

    int A = g_acount[prob];
    const float4* __restrict__ al = g_alist[prob];

    int ltc = 0, tpc = 0;
    for (int n = warp; n < NPTS; n += nwarps) {
        if (targ_clses[b * NPTS + n] != cls) continue;   // warp-uniform
        int d = n >> 10, h = (n >> 5) & 31, w = n & 31;
        float t0 = targ_boxes[(b * NPTS + n) * 3 + 0];
        float t1 = targ_boxes[(b * NPTS + n) * 3 + 1];
        float t2 = targ_boxes[(b * NPTS + n) * 3 + 2];
        float tz = __fmul_rn(__fdiv_rn(__fadd_rn((float)d, t0),  4.0f),  3.0f);
        float ty = __fmul_rn(__fdiv_rn(__fadd_rn((float)h, t1), 32.0f), 25.0f);
        float tx = __fmul_rn(__fdiv_rn(__fadd_rn((float)w, t2), 32.0f), 25.0f);
        if (!(tz >= 0.0f && tz < HI)) continue;
        ltc++;
        float bb = __fadd_rn(__fadd_rn(__fmul_rn(tz, tz), __fmul_rn(ty, ty)),
                             __fmul_rn(tx, tx));
        bool found = false;
        for (int a0 = 0; a0 < A && !found; a0 += 256) {
            bool hit = false;
            #pragma unroll
            for (int k = 0; k < 8; k++) {
                int a = a0 + (k << 5) + lane;
                if (a < A) {
                    float4 p = al[a];
                    float dot = __fadd_rn(__fadd_rn(__fmul_rn(p.x, tz),
                                                    __fmul_rn(p.y, ty)),
                                          __fmul_rn(p.z, tx));
                    float dist = __fsub_rn(__fadd_rn(p.w, bb), __fmul_rn(2.0f, dot));
                    hit |= (dist < c2);
                }
            }
            found = (__ballot_sync(0xFFFFFFFFu, hit) != 0);
        }
        if (found) tpc++;
    }
    if (lane == 0 && (ltc | tpc)) {
        if (ltc) atomicAdd(&g_cnt[prob][2], ltc);
        if (tpc) atomicAdd(&g_cnt[prob][0], tpc);
    }
}

// ---------------------------------------------------------------------------
// Kernel 5: finalize — out[(b*2+ci)*3 + {0,1,2}] = {tp, fp, fn} as float32
// ---------------------------------------------------------------------------
__global__ void k_final(float* __restrict__ out)
{
    int p = threadIdx.x;
    if (p < NPROB) {
        int tp = g_cnt[p][0], lp = g_cnt[p][1], lt = g_cnt[p][2];
        out[p * 3 + 0] = (float)tp;
        out[p * 3 + 1] = (float)(lp - tp);
        out[p * 3 + 2] = (float)(lt - tp);
    }
}

extern "C" void kernel_launch(void* const* d_in, const int* in_sizes, int n_in,
                              void* d_out, int out_size)
{
    const float* pred_clses = (const float*)d_in[0];
    const float* pred_boxes = (const float*)d_in[1];
    const int*   targ_clses = (const int*)d_in[2];
    const float* targ_boxes = (const float*)d_in[3];
    float* out = (float*)d_out;

    k_prep_sort<<<NPROB, 1024>>>(pred_clses, pred_boxes);
    k_conflict<<<dim3(32, NPROB), 256>>>();
    k_nms<<<NPROB, 1024>>>();
    k_match<<<dim3(16, NPROB), 256>>>(targ_clses, targ_boxes);
    k_final<<<1, 32>>>(out);
}